// round 2
// baseline (speedup 1.0000x reference)
#include <cuda_runtime.h>
#include <cuda_bf16.h>

#define SRC_H 512
#define SRC_W 512
#define NCH   3
#define OUT_N 224
#define TOX   32   // output tile width
#define TOY   8    // output tile height
#define NTAP  6
#define NIX   79   // warped tile width  (covers floor-span 72 + 5 taps + jitter pad)
#define NIY   24   // warped tile height (covers floor-span 17 + 5 taps + jitter pad)
#define NTHREADS 256

__global__ __launch_bounds__(NTHREADS) void warp_resize_kernel(
    const float* __restrict__ images,   // (32, 512, 512, 3)
    const float* __restrict__ mats,     // (32, 2, 3)
    float* __restrict__ out)            // (32, 224, 224, 3)
{
    __shared__ float s_w[NCH][NIY][NIX];     // warped tile
    __shared__ float s_t[NCH][NIY][TOX];     // after x-convolution
    __shared__ float s_wx[TOX][NTAP];
    __shared__ float s_wy[TOY][NTAP];
    __shared__ int   s_bx[TOX];
    __shared__ int   s_by[TOY];

    const int b   = blockIdx.z;
    const int ox0 = blockIdx.x * TOX;
    const int oy0 = blockIdx.y * TOY;
    const int tid = threadIdx.x;

    const float INV = 512.0f / 224.0f;   // inv_scale = kernel_scale (antialias downscale)
    const float SC  = 224.0f / 512.0f;

    // Warped-space tile base (tap base of the first output row/col of the tile)
    const int IX0 = (int)floorf((ox0 + 0.5f) * INV - 0.5f) - 2;
    const int IY0 = (int)floorf((oy0 + 0.5f) * INV - 0.5f) - 2;

    // ---- Resize weights (normalized triangle kernel, jax semantics) ----
    if (tid < TOX) {
        int j = ox0 + tid;
        float sf = (j + 0.5f) * INV - 0.5f;
        int i0 = (int)floorf(sf) - 2;
        float wv[NTAP];
        float sum = 0.0f;
        #pragma unroll
        for (int k = 0; k < NTAP; k++) {
            int i = i0 + k;
            float w = fmaxf(1.0f - fabsf(sf - (float)i) * SC, 0.0f);
            if (i < 0 || i >= SRC_W) w = 0.0f;
            wv[k] = w; sum += w;
        }
        float inv = 1.0f / sum;
        #pragma unroll
        for (int k = 0; k < NTAP; k++) s_wx[tid][k] = wv[k] * inv;
        s_bx[tid] = i0 - IX0;
    } else if (tid < TOX + TOY) {
        int t = tid - TOX;
        int j = oy0 + t;
        float sf = (j + 0.5f) * INV - 0.5f;
        int i0 = (int)floorf(sf) - 2;
        float wv[NTAP];
        float sum = 0.0f;
        #pragma unroll
        for (int k = 0; k < NTAP; k++) {
            int i = i0 + k;
            float w = fmaxf(1.0f - fabsf(sf - (float)i) * SC, 0.0f);
            if (i < 0 || i >= SRC_H) w = 0.0f;
            wv[k] = w; sum += w;
        }
        float inv = 1.0f / sum;
        #pragma unroll
        for (int k = 0; k < NTAP; k++) s_wy[t][k] = wv[k] * inv;
        s_by[t] = i0 - IY0;
    }

    // ---- Affine matrix for this batch ----
    const float* Mp = mats + b * 6;
    const float M00 = __ldg(Mp + 0), M01 = __ldg(Mp + 1), M02 = __ldg(Mp + 2);
    const float M10 = __ldg(Mp + 3), M11 = __ldg(Mp + 4), M12 = __ldg(Mp + 5);

    const float* img = images + (size_t)b * SRC_H * SRC_W * NCH;

    // ---- Stage 1: compute warped tile (affine + zero-padded bilerp) ----
    for (int idx = tid; idx < NIY * NIX; idx += NTHREADS) {
        int ty = idx / NIX;
        int tx = idx - ty * NIX;
        float gy = (float)(IY0 + ty);
        float gx = (float)(IX0 + tx);
        float sy = fmaf(M00, gy, fmaf(M01, gx, M02));
        float sx = fmaf(M10, gy, fmaf(M11, gx, M12));
        float fy = floorf(sy), fx = floorf(sx);
        float ay = sy - fy,   ax = sx - fx;
        int y0 = (int)fy, x0 = (int)fx;

        float r = 0.0f, g = 0.0f, bl = 0.0f;
        #pragma unroll
        for (int dy = 0; dy < 2; dy++) {
            int yi = y0 + dy;
            float wy = dy ? ay : (1.0f - ay);
            bool vy = (yi >= 0) & (yi < SRC_H);
            #pragma unroll
            for (int dx = 0; dx < 2; dx++) {
                int xi = x0 + dx;
                float w = wy * (dx ? ax : (1.0f - ax));
                if (vy & (xi >= 0) & (xi < SRC_W)) {
                    const float* p = img + ((size_t)yi * SRC_W + xi) * NCH;
                    r  = fmaf(w, p[0], r);
                    g  = fmaf(w, p[1], g);
                    bl = fmaf(w, p[2], bl);
                }
            }
        }
        s_w[0][ty][tx] = r;
        s_w[1][ty][tx] = g;
        s_w[2][ty][tx] = bl;
    }
    __syncthreads();

    // ---- Stage 2: x-convolution (6 taps) ----
    for (int idx = tid; idx < NIY * TOX; idx += NTHREADS) {
        int ty = idx / TOX;
        int ox = idx - ty * TOX;
        int base = s_bx[ox];
        float a0 = 0.0f, a1 = 0.0f, a2 = 0.0f;
        #pragma unroll
        for (int k = 0; k < NTAP; k++) {
            float w = s_wx[ox][k];
            a0 = fmaf(w, s_w[0][ty][base + k], a0);
            a1 = fmaf(w, s_w[1][ty][base + k], a1);
            a2 = fmaf(w, s_w[2][ty][base + k], a2);
        }
        s_t[0][ty][ox] = a0;
        s_t[1][ty][ox] = a1;
        s_t[2][ty][ox] = a2;
    }
    __syncthreads();

    // ---- Stage 3: y-convolution (6 taps) + coalesced store ----
    {
        int oy = tid / TOX;      // 0..7  (256 = 8*32 exactly)
        int ox = tid - oy * TOX; // 0..31
        int base = s_by[oy];
        float a0 = 0.0f, a1 = 0.0f, a2 = 0.0f;
        #pragma unroll
        for (int k = 0; k < NTAP; k++) {
            float w = s_wy[oy][k];
            a0 = fmaf(w, s_t[0][base + k][ox], a0);
            a1 = fmaf(w, s_t[1][base + k][ox], a1);
            a2 = fmaf(w, s_t[2][base + k][ox], a2);
        }
        float* op = out + (((size_t)b * OUT_N + (oy0 + oy)) * OUT_N + (ox0 + ox)) * NCH;
        op[0] = a0;
        op[1] = a1;
        op[2] = a2;
    }
}

extern "C" void kernel_launch(void* const* d_in, const int* in_sizes, int n_in,
                              void* d_out, int out_size)
{
    const float* images = (const float*)d_in[0];   // 32*512*512*3 floats
    const float* mats   = (const float*)d_in[1];   // 32*2*3 floats
    float* out = (float*)d_out;                    // 32*224*224*3 floats

    dim3 grid(OUT_N / TOX, OUT_N / TOY, 32);       // 7 x 28 x 32
    warp_resize_kernel<<<grid, NTHREADS>>>(images, mats, out);
}